// round 1
// baseline (speedup 1.0000x reference)
#include <cuda_runtime.h>

#define NB 4
#define LL 8192
#define SSZ 8192
#define HH 8
#define DD 64
#define NH (NB * HH)
#define EPS 1e-6f

// scratch: per-(n,h) KV state [64x64] and k-sum [64]
__device__ float g_kv[NH * DD * DD];
__device__ float g_ksum[NH * DD];

__device__ __forceinline__ float fmap(float x) {
    return x > 0.f ? x + 1.f : __expf(x);
}

__global__ void zero_kernel() {
    int i = blockIdx.x * blockDim.x + threadIdx.x;
    if (i < NH * DD * DD) g_kv[i] = 0.f;
    if (i < NH * DD) g_ksum[i] = 0.f;
}

// Kernel A: kv[nh][d][v] += sum_s kf[s][d] * vm[s][v]; ksum[nh][d] += sum_s kf[s][d]
// grid: (NH, SCHUNKS=32), block: 256 threads (16x16), each thread owns 4x4 of the 64x64 tile.
__global__ __launch_bounds__(256) void kv_kernel(
    const float* __restrict__ kin, const float* __restrict__ vin,
    const float* __restrict__ kv_mask)
{
    __shared__ float ks[32][64];
    __shared__ float vs[32][64];

    const int nh = blockIdx.x;
    const int n = nh >> 3, h = nh & 7;
    const int s0 = blockIdx.y * 256;   // 8192 / 32 chunks
    const int t = threadIdx.x;
    const int tx = t & 15, ty = t >> 4;

    float acc[4][4] = {};
    float ksl = 0.f;

    for (int st = 0; st < 256; st += 32) {
        // load + featurize a 32x64 tile of k and v
        #pragma unroll
        for (int e = 0; e < 8; e++) {
            int idx = t + e * 256;
            int r = idx >> 6, c = idx & 63;
            int s = s0 + st + r;
            float m = kv_mask[n * SSZ + s];
            size_t g = (((size_t)(n * SSZ + s)) * HH + h) * DD + c;
            float kx = kin[g];
            ks[r][c] = fmap(kx) * m;
            vs[r][c] = vin[g] * m;
        }
        __syncthreads();

        #pragma unroll 8
        for (int s = 0; s < 32; s++) {
            float4 a = *(const float4*)&ks[s][ty * 4];
            float4 b = *(const float4*)&vs[s][tx * 4];
            acc[0][0] += a.x * b.x; acc[0][1] += a.x * b.y;
            acc[0][2] += a.x * b.z; acc[0][3] += a.x * b.w;
            acc[1][0] += a.y * b.x; acc[1][1] += a.y * b.y;
            acc[1][2] += a.y * b.z; acc[1][3] += a.y * b.w;
            acc[2][0] += a.z * b.x; acc[2][1] += a.z * b.y;
            acc[2][2] += a.z * b.z; acc[2][3] += a.z * b.w;
            acc[3][0] += a.w * b.x; acc[3][1] += a.w * b.y;
            acc[3][2] += a.w * b.z; acc[3][3] += a.w * b.w;
        }
        if (t < 64) {
            #pragma unroll
            for (int s = 0; s < 32; s++) ksl += ks[s][t];
        }
        __syncthreads();
    }

    #pragma unroll
    for (int i = 0; i < 4; i++)
        #pragma unroll
        for (int j = 0; j < 4; j++)
            atomicAdd(&g_kv[nh * 4096 + (ty * 4 + i) * 64 + (tx * 4 + j)], acc[i][j]);
    if (t < 64) atomicAdd(&g_ksum[nh * 64 + t], ksl);
}

// Kernel B: out[n,l,h,v] = (qf . kv[:,v]) / (qf . ksum + eps)
// grid: (NH, 64 l-chunks of 128 rows). 256 threads = 8 warps x 16 rows.
__global__ __launch_bounds__(256) void out_kernel(
    const float* __restrict__ qin, const float* __restrict__ q_mask,
    float* __restrict__ out)
{
    __shared__ float2 kv2[64][32];       // [d][v-pair], same layout as float[64][64]
    __shared__ float ksum_s[64];
    __shared__ float qbuf[8][4][64];     // per-warp, 4 rows of featurized q

    const int nh = blockIdx.x;
    const int n = nh >> 3, h = nh & 7;
    const int l0 = blockIdx.y * 128;
    const int t = threadIdx.x;
    const int w = t >> 5, lane = t & 31;

    float* kvf = (float*)kv2;
    #pragma unroll
    for (int e = t; e < 4096; e += 256) kvf[e] = g_kv[nh * 4096 + e];
    if (t < 64) ksum_s[t] = g_ksum[nh * 64 + t];
    __syncthreads();

    const float ks0 = ksum_s[2 * lane];
    const float ks1 = ksum_s[2 * lane + 1];

    for (int g = 0; g < 4; g++) {
        float dv[4];
        size_t base[4];
        #pragma unroll
        for (int r = 0; r < 4; r++) {
            int l = l0 + w * 16 + g * 4 + r;
            base[r] = (((size_t)(n * LL + l)) * HH + h) * DD;
            float2 x = *(const float2*)&qin[base[r] + 2 * lane];
            float qm = q_mask[n * LL + l];
            float f0 = fmap(x.x) * qm;
            float f1 = fmap(x.y) * qm;
            qbuf[w][r][2 * lane] = f0;
            qbuf[w][r][2 * lane + 1] = f1;
            float p = f0 * ks0 + f1 * ks1;
            #pragma unroll
            for (int o = 16; o; o >>= 1) p += __shfl_xor_sync(0xffffffffu, p, o);
            dv[r] = 1.f / (p + EPS);
        }
        __syncwarp();

        float acc[4][2] = {};
        #pragma unroll 8
        for (int d = 0; d < 64; d++) {
            float2 c = kv2[d][lane];
            #pragma unroll
            for (int r = 0; r < 4; r++) {
                float qd = qbuf[w][r][d];
                acc[r][0] += qd * c.x;
                acc[r][1] += qd * c.y;
            }
        }
        #pragma unroll
        for (int r = 0; r < 4; r++) {
            ((float2*)&out[base[r]])[lane] =
                make_float2(acc[r][0] * dv[r], acc[r][1] * dv[r]);
        }
        __syncwarp();   // qbuf reused next g
    }
}

extern "C" void kernel_launch(void* const* d_in, const int* in_sizes, int n_in,
                              void* d_out, int out_size)
{
    const float* q   = (const float*)d_in[0];
    const float* k   = (const float*)d_in[1];
    const float* v   = (const float*)d_in[2];
    const float* qm  = (const float*)d_in[3];
    const float* kvm = (const float*)d_in[4];
    float* out = (float*)d_out;

    zero_kernel<<<(NH * DD * DD + 255) / 256, 256>>>();
    kv_kernel<<<dim3(NH, 32), 256>>>(k, v, kvm);
    out_kernel<<<dim3(NH, 64), 256>>>(q, qm, out);
}

// round 2
// speedup vs baseline: 1.0824x; 1.0824x over previous
#include <cuda_runtime.h>

#define NB 4
#define LL 8192
#define SSZ 8192
#define HH 8
#define DD 64
#define NH (NB * HH)
#define EPS 1e-6f

typedef unsigned long long u64;

__device__ float g_kv[NH * DD * DD];
__device__ float g_ksum[NH * DD];

__device__ __forceinline__ float fmap(float x) {
    return x > 0.f ? x + 1.f : __expf(x);
}

__device__ __forceinline__ u64 splat2(float a) {
    u64 r;
    asm("mov.b64 %0, {%1, %1};" : "=l"(r) : "f"(a));
    return r;
}

__device__ __forceinline__ u64 ffma2(u64 a, u64 b, u64 c) {
    u64 d;
    asm("fma.rn.f32x2 %0, %1, %2, %3;" : "=l"(d) : "l"(a), "l"(b), "l"(c));
    return d;
}

__device__ __forceinline__ void unpack2(u64 p, float& lo, float& hi) {
    asm("mov.b64 {%0, %1}, %2;" : "=f"(lo), "=f"(hi) : "l"(p));
}

__global__ void zero_kernel() {
    int i = blockIdx.x * blockDim.x + threadIdx.x;
    if (i < NH * DD * DD) g_kv[i] = 0.f;
    if (i < NH * DD) g_ksum[i] = 0.f;
}

// Kernel A: kv[nh][d][v] = sum_s kf[s][d]*vm[s][v]; ksum[nh][d] = sum_s kf[s][d]
// grid (NH, 64): each block reduces a 128-s chunk. 64 threads, 8x8 register tile, FFMA2.
__global__ __launch_bounds__(64) void kv_kernel(
    const float* __restrict__ kin, const float* __restrict__ vin,
    const float* __restrict__ kv_mask)
{
    __shared__ float ks[32][64];
    __shared__ float vs[32][64];

    const int nh = blockIdx.x;
    const int n = nh >> 3, h = nh & 7;
    const int s0 = blockIdx.y * 128;
    const int t = threadIdx.x;
    const int tx = t & 7, ty = t >> 3;

    u64 acc2[8][4] = {};
    float ksl = 0.f;

    for (int st = 0; st < 128; st += 32) {
        #pragma unroll
        for (int e = 0; e < 8; e++) {
            int idx = t + e * 64;
            int r = idx >> 4, c4 = (idx & 15) * 4;
            int s = s0 + st + r;
            float m = kv_mask[n * SSZ + s];
            size_t g = (((size_t)(n * SSZ + s)) * HH + h) * DD + c4;
            float4 kq = *(const float4*)&kin[g];
            float4 vq = *(const float4*)&vin[g];
            float4 kf4 = make_float4(fmap(kq.x) * m, fmap(kq.y) * m,
                                     fmap(kq.z) * m, fmap(kq.w) * m);
            float4 vm4 = make_float4(vq.x * m, vq.y * m, vq.z * m, vq.w * m);
            *(float4*)&ks[r][c4] = kf4;
            *(float4*)&vs[r][c4] = vm4;
        }
        __syncthreads();

        #pragma unroll 4
        for (int s = 0; s < 32; s++) {
            float4 a0 = *(const float4*)&ks[s][ty * 8];
            float4 a1 = *(const float4*)&ks[s][ty * 8 + 4];
            float4 b0 = *(const float4*)&vs[s][tx * 8];
            float4 b1 = *(const float4*)&vs[s][tx * 8 + 4];
            ksl += ks[s][t];
            float a[8] = {a0.x, a0.y, a0.z, a0.w, a1.x, a1.y, a1.z, a1.w};
            u64 b2[4];
            b2[0] = ((const u64*)&b0)[0];
            b2[1] = ((const u64*)&b0)[1];
            b2[2] = ((const u64*)&b1)[0];
            b2[3] = ((const u64*)&b1)[1];
            #pragma unroll
            for (int i = 0; i < 8; i++) {
                u64 as = splat2(a[i]);
                #pragma unroll
                for (int j = 0; j < 4; j++)
                    acc2[i][j] = ffma2(as, b2[j], acc2[i][j]);
            }
        }
        __syncthreads();
    }

    #pragma unroll
    for (int i = 0; i < 8; i++) {
        int row = ty * 8 + i;
        #pragma unroll
        for (int j = 0; j < 4; j++) {
            float lo, hi;
            unpack2(acc2[i][j], lo, hi);
            atomicAdd(&g_kv[nh * 4096 + row * 64 + tx * 8 + 2 * j], lo);
            atomicAdd(&g_kv[nh * 4096 + row * 64 + tx * 8 + 2 * j + 1], hi);
        }
    }
    atomicAdd(&g_ksum[nh * 64 + t], ksl);
}

// Kernel B: out[n,l,h,v] = (qf . kv[:,v]) / (qf . ksum + eps)
// grid (NH, 128): 64 l-rows per block, 64 threads, 8x8 register tile, FFMA2.
__global__ __launch_bounds__(64) void out_kernel(
    const float* __restrict__ qin, const float* __restrict__ q_mask,
    float* __restrict__ out)
{
    __shared__ float qs[64][65];     // pad 65: bank = (l + d) % 32
    __shared__ float kvs[64][64];    // d-major
    __shared__ float ksum_s[64];
    __shared__ float div_s[64];

    const int nh = blockIdx.x;
    const int n = nh >> 3, h = nh & 7;
    const int l0 = blockIdx.y * 64;
    const int t = threadIdx.x;
    const int tx = t & 7, ty = t >> 3;

    // load kv state (L2 resident) + ksum
    const float4* kvg = (const float4*)&g_kv[nh * 4096];
    #pragma unroll
    for (int e = 0; e < 16; e++)
        ((float4*)kvs)[t + e * 64] = kvg[t + e * 64];
    ksum_s[t] = g_ksum[nh * 64 + t];

    // load + featurize q tile
    #pragma unroll
    for (int e = 0; e < 16; e++) {
        int idx = t + e * 64;
        int l = idx >> 4, c4 = (idx & 15) * 4;
        float m = q_mask[n * LL + l0 + l];
        size_t g = (((size_t)(n * LL + l0 + l)) * HH + h) * DD + c4;
        float4 x = *(const float4*)&qin[g];
        qs[l][c4 + 0] = fmap(x.x) * m;
        qs[l][c4 + 1] = fmap(x.y) * m;
        qs[l][c4 + 2] = fmap(x.z) * m;
        qs[l][c4 + 3] = fmap(x.w) * m;
    }
    __syncthreads();

    // normalizer: thread t owns row t
    {
        float p = 0.f;
        #pragma unroll 16
        for (int d = 0; d < 64; d++)
            p += qs[t][d] * ksum_s[d];
        div_s[t] = 1.f / (p + EPS);
    }
    __syncthreads();

    u64 acc2[8][4] = {};
    #pragma unroll 4
    for (int d = 0; d < 64; d++) {
        float4 b0 = *(const float4*)&kvs[d][tx * 8];
        float4 b1 = *(const float4*)&kvs[d][tx * 8 + 4];
        u64 b2[4];
        b2[0] = ((const u64*)&b0)[0];
        b2[1] = ((const u64*)&b0)[1];
        b2[2] = ((const u64*)&b1)[0];
        b2[3] = ((const u64*)&b1)[1];
        #pragma unroll
        for (int i = 0; i < 8; i++) {
            u64 as = splat2(qs[ty * 8 + i][d]);
            #pragma unroll
            for (int j = 0; j < 4; j++)
                acc2[i][j] = ffma2(as, b2[j], acc2[i][j]);
        }
    }

    #pragma unroll
    for (int i = 0; i < 8; i++) {
        int l = l0 + ty * 8 + i;
        float dv = div_s[ty * 8 + i];
        float o[8];
        #pragma unroll
        for (int j = 0; j < 4; j++) {
            float lo, hi;
            unpack2(acc2[i][j], lo, hi);
            o[2 * j] = lo * dv;
            o[2 * j + 1] = hi * dv;
        }
        size_t g = (((size_t)(n * LL + l)) * HH + h) * DD + tx * 8;
        *(float4*)&out[g] = make_float4(o[0], o[1], o[2], o[3]);
        *(float4*)&out[g + 4] = make_float4(o[4], o[5], o[6], o[7]);
    }
}

extern "C" void kernel_launch(void* const* d_in, const int* in_sizes, int n_in,
                              void* d_out, int out_size)
{
    const float* q   = (const float*)d_in[0];
    const float* k   = (const float*)d_in[1];
    const float* v   = (const float*)d_in[2];
    const float* qm  = (const float*)d_in[3];
    const float* kvm = (const float*)d_in[4];
    float* out = (float*)d_out;

    zero_kernel<<<(NH * DD * DD + 255) / 256, 256>>>();
    kv_kernel<<<dim3(NH, 64), 64>>>(k, v, kvm);
    out_kernel<<<dim3(NH, 128), 64>>>(q, qm, out);
}

// round 4
// speedup vs baseline: 1.1728x; 1.0835x over previous
#include <cuda_runtime.h>

#define NB 4
#define LL 8192
#define SSZ 8192
#define HH 8
#define DD 64
#define NH (NB * HH)
#define CH 32            // s-chunks per (n,h); 256 s per chunk
#define PART_STRIDE 4160 // 4096 kv + 64 ksum
#define EPS 1e-6f

typedef unsigned long long u64;

__device__ float g_part[NH * CH * PART_STRIDE];
__device__ float g_kv[NH * DD * DD];
__device__ float g_ksum[NH * DD];

__device__ __forceinline__ float fmap(float x) {
    return x > 0.f ? x + 1.f : __expf(x);
}

__device__ __forceinline__ u64 splat2(float a) {
    u64 r;
    asm("mov.b64 %0, {%1, %1};" : "=l"(r) : "f"(a));
    return r;
}

__device__ __forceinline__ u64 ffma2(u64 a, u64 b, u64 c) {
    u64 d;
    asm("fma.rn.f32x2 %0, %1, %2, %3;" : "=l"(d) : "l"(a), "l"(b), "l"(c));
    return d;
}

// Kernel A: partial kv over a 256-s chunk. No atomics, no pre-zero.
// 64 threads; per-thread 8x8 fragment split 4+4 to avoid 128B bank wrap.
__global__ __launch_bounds__(64) void kv_partial_kernel(
    const float* __restrict__ kin, const float* __restrict__ vin,
    const float* __restrict__ kv_mask)
{
    __shared__ float ks[2][16][64];
    __shared__ float vs[2][16][64];

    const int nh = blockIdx.x;
    const int n = nh >> 3, h = nh & 7;
    const int s0 = blockIdx.y * 256;
    const int t = threadIdx.x;
    const int tx = t & 7, ty = t >> 3;

    u64 acc2[8][4] = {};
    float ksl = 0.f;

    float4 kr[4], vr[4];

    // prologue: load tile 0
    #pragma unroll
    for (int e = 0; e < 4; e++) {
        int idx = t + e * 64;
        int r = idx >> 4, c4 = (idx & 15) * 4;
        int s = s0 + r;
        float m = kv_mask[n * SSZ + s];
        size_t g = (((size_t)(n * SSZ + s)) * HH + h) * DD + c4;
        float4 kq = *(const float4*)&kin[g];
        float4 vq = *(const float4*)&vin[g];
        kr[e] = make_float4(fmap(kq.x) * m, fmap(kq.y) * m, fmap(kq.z) * m, fmap(kq.w) * m);
        vr[e] = make_float4(vq.x * m, vq.y * m, vq.z * m, vq.w * m);
    }
    #pragma unroll
    for (int e = 0; e < 4; e++) {
        int idx = t + e * 64;
        int r = idx >> 4, c4 = (idx & 15) * 4;
        *(float4*)&ks[0][r][c4] = kr[e];
        *(float4*)&vs[0][r][c4] = vr[e];
    }
    __syncthreads();

    #pragma unroll 1
    for (int tile = 0; tile < 16; tile++) {
        const int cur = tile & 1;

        // prefetch next tile into registers
        if (tile < 15) {
            #pragma unroll
            for (int e = 0; e < 4; e++) {
                int idx = t + e * 64;
                int r = idx >> 4, c4 = (idx & 15) * 4;
                int s = s0 + (tile + 1) * 16 + r;
                float m = kv_mask[n * SSZ + s];
                size_t g = (((size_t)(n * SSZ + s)) * HH + h) * DD + c4;
                float4 kq = *(const float4*)&kin[g];
                float4 vq = *(const float4*)&vin[g];
                kr[e] = make_float4(fmap(kq.x) * m, fmap(kq.y) * m,
                                    fmap(kq.z) * m, fmap(kq.w) * m);
                vr[e] = make_float4(vq.x * m, vq.y * m, vq.z * m, vq.w * m);
            }
        }

        // compute on current tile
        #pragma unroll 4
        for (int s = 0; s < 16; s++) {
            float4 a0 = *(const float4*)&ks[cur][s][ty * 4];
            float4 a1 = *(const float4*)&ks[cur][s][32 + ty * 4];
            float4 b0 = *(const float4*)&vs[cur][s][tx * 4];
            float4 b1 = *(const float4*)&vs[cur][s][32 + tx * 4];
            ksl += ks[cur][s][t];
            float a[8] = {a0.x, a0.y, a0.z, a0.w, a1.x, a1.y, a1.z, a1.w};
            u64 b2[4];
            b2[0] = ((const u64*)&b0)[0];
            b2[1] = ((const u64*)&b0)[1];
            b2[2] = ((const u64*)&b1)[0];
            b2[3] = ((const u64*)&b1)[1];
            #pragma unroll
            for (int i = 0; i < 8; i++) {
                u64 as = splat2(a[i]);
                #pragma unroll
                for (int j = 0; j < 4; j++)
                    acc2[i][j] = ffma2(as, b2[j], acc2[i][j]);
            }
        }

        // stage next tile into the other buffer
        if (tile < 15) {
            #pragma unroll
            for (int e = 0; e < 4; e++) {
                int idx = t + e * 64;
                int r = idx >> 4, c4 = (idx & 15) * 4;
                *(float4*)&ks[cur ^ 1][r][c4] = kr[e];
                *(float4*)&vs[cur ^ 1][r][c4] = vr[e];
            }
        }
        __syncthreads();
    }

    // write partials (no atomics)
    float* part = &g_part[(nh * CH + blockIdx.y) * PART_STRIDE];
    #pragma unroll
    for (int i = 0; i < 8; i++) {
        int row = (i < 4) ? (ty * 4 + i) : (32 + ty * 4 + i - 4);
        float4 f0, f1;
        ((u64*)&f0)[0] = acc2[i][0];
        ((u64*)&f0)[1] = acc2[i][1];
        ((u64*)&f1)[0] = acc2[i][2];
        ((u64*)&f1)[1] = acc2[i][3];
        *(float4*)&part[row * 64 + tx * 4] = f0;
        *(float4*)&part[row * 64 + 32 + tx * 4] = f1;
    }
    part[4096 + t] = ksl;
}

// Reduce 32 partials -> final kv + ksum. 520*256 == 32*4160 exactly.
__global__ __launch_bounds__(256) void kv_reduce_kernel() {
    int idx = blockIdx.x * 256 + threadIdx.x;
    int nh = idx / PART_STRIDE;
    int el = idx - nh * PART_STRIDE;
    float s = 0.f;
    #pragma unroll 8
    for (int ch = 0; ch < CH; ch++)
        s += g_part[(nh * CH + ch) * PART_STRIDE + el];
    if (el < 4096) g_kv[nh * 4096 + el] = s;
    else           g_ksum[nh * 64 + el - 4096] = s;
}

// Kernel B: out = (qf . kv) / (qf . ksum + eps). 128 threads, 128 l-rows/CTA.
// Shared arrays live in DYNAMIC smem (50432 B > 48KB static limit).
#define OUT_SMEM_BYTES (128 * 65 * 4 + 64 * 64 * 4 + 64 * 4 + 128 * 4)

__global__ __launch_bounds__(128) void out_kernel(
    const float* __restrict__ qin, const float* __restrict__ q_mask,
    float* __restrict__ out)
{
    extern __shared__ float dynbuf[];
    float (*qs)[65]  = (float(*)[65])dynbuf;                  // 128*65
    float (*kvs)[64] = (float(*)[64])(dynbuf + 128 * 65);     // 64*64
    float* ksum_s    = dynbuf + 128 * 65 + 64 * 64;           // 64
    float* div_s     = ksum_s + 64;                           // 128

    const int nh = blockIdx.x;
    const int n = nh >> 3, h = nh & 7;
    const int l0 = blockIdx.y * 128;
    const int t = threadIdx.x;
    const int tx = t & 7, ty = t >> 3;   // ty 0..15

    const float4* kvg = (const float4*)&g_kv[nh * 4096];
    #pragma unroll
    for (int e = 0; e < 8; e++)
        ((float4*)kvs)[t + e * 128] = kvg[t + e * 128];
    if (t < 64) ksum_s[t] = g_ksum[nh * 64 + t];

    #pragma unroll
    for (int e = 0; e < 16; e++) {
        int idx = t + e * 128;
        int l = idx >> 4, c4 = (idx & 15) * 4;
        float m = q_mask[n * LL + l0 + l];
        size_t g = (((size_t)(n * LL + l0 + l)) * HH + h) * DD + c4;
        float4 x = *(const float4*)&qin[g];
        qs[l][c4 + 0] = fmap(x.x) * m;
        qs[l][c4 + 1] = fmap(x.y) * m;
        qs[l][c4 + 2] = fmap(x.z) * m;
        qs[l][c4 + 3] = fmap(x.w) * m;
    }
    __syncthreads();

    {
        float p = 0.f;
        #pragma unroll 16
        for (int d = 0; d < 64; d++)
            p += qs[t][d] * ksum_s[d];
        div_s[t] = 1.f / (p + EPS);
    }
    __syncthreads();

    u64 acc2[8][4] = {};
    #pragma unroll 4
    for (int d = 0; d < 64; d++) {
        float4 b0 = *(const float4*)&kvs[d][tx * 4];
        float4 b1 = *(const float4*)&kvs[d][32 + tx * 4];
        u64 b2[4];
        b2[0] = ((const u64*)&b0)[0];
        b2[1] = ((const u64*)&b0)[1];
        b2[2] = ((const u64*)&b1)[0];
        b2[3] = ((const u64*)&b1)[1];
        #pragma unroll
        for (int i = 0; i < 8; i++) {
            int row = (i < 4) ? (ty * 4 + i) : (64 + ty * 4 + i - 4);
            u64 as = splat2(qs[row][d]);
            #pragma unroll
            for (int j = 0; j < 4; j++)
                acc2[i][j] = ffma2(as, b2[j], acc2[i][j]);
        }
    }

    #pragma unroll
    for (int i = 0; i < 8; i++) {
        int rl = (i < 4) ? (ty * 4 + i) : (64 + ty * 4 + i - 4);
        int l = l0 + rl;
        float dv = div_s[rl];
        float4 f0, f1;
        ((u64*)&f0)[0] = acc2[i][0];
        ((u64*)&f0)[1] = acc2[i][1];
        ((u64*)&f1)[0] = acc2[i][2];
        ((u64*)&f1)[1] = acc2[i][3];
        f0.x *= dv; f0.y *= dv; f0.z *= dv; f0.w *= dv;
        f1.x *= dv; f1.y *= dv; f1.z *= dv; f1.w *= dv;
        size_t g = (((size_t)(n * LL + l)) * HH + h) * DD;
        *(float4*)&out[g + tx * 4] = f0;
        *(float4*)&out[g + 32 + tx * 4] = f1;
    }
}

extern "C" void kernel_launch(void* const* d_in, const int* in_sizes, int n_in,
                              void* d_out, int out_size)
{
    const float* q   = (const float*)d_in[0];
    const float* k   = (const float*)d_in[1];
    const float* v   = (const float*)d_in[2];
    const float* qm  = (const float*)d_in[3];
    const float* kvm = (const float*)d_in[4];
    float* out = (float*)d_out;

    static bool attr_done = false;
    if (!attr_done) {
        cudaFuncSetAttribute(out_kernel,
                             cudaFuncAttributeMaxDynamicSharedMemorySize,
                             OUT_SMEM_BYTES);
        attr_done = true;
    }

    kv_partial_kernel<<<dim3(NH, CH), 64>>>(k, v, kvm);
    kv_reduce_kernel<<<(NH * PART_STRIDE) / 256, 256>>>();
    out_kernel<<<dim3(NH, 64), 128, OUT_SMEM_BYTES>>>(q, qm, out);
}

// round 6
// speedup vs baseline: 1.3868x; 1.1825x over previous
#include <cuda_runtime.h>

#define NB 4
#define LL 8192
#define SSZ 8192
#define HH 8
#define DD 64
#define NH (NB * HH)
#define CH 32            // s-chunks per (n,h); 256 s per chunk
#define PART_STRIDE 4160 // 4096 kv + 64 ksum
#define EPS 1e-6f
#define QPAD 68          // q row stride: 16B-aligned, bank-shift 4/row

typedef unsigned long long u64;

__device__ float g_part[NH * CH * PART_STRIDE];
__device__ float g_kv[NH * DD * DD];
__device__ float g_ksum[NH * DD];

__device__ __forceinline__ float fmap(float x) {
    return x > 0.f ? x + 1.f : __expf(x);
}

__device__ __forceinline__ u64 splat2(float a) {
    u64 r;
    asm("mov.b64 %0, {%1, %1};" : "=l"(r) : "f"(a));
    return r;
}

__device__ __forceinline__ u64 ffma2(u64 a, u64 b, u64 c) {
    u64 d;
    asm("fma.rn.f32x2 %0, %1, %2, %3;" : "=l"(d) : "l"(a), "l"(b), "l"(c));
    return d;
}

// Kernel A: partial kv over a 256-s chunk. No atomics, no pre-zero.
// 64 threads, 8 CTAs/SM (128-reg cap). 8x8 fragment split 4+4 (no 128B wrap).
__global__ __launch_bounds__(64, 8) void kv_partial_kernel(
    const float* __restrict__ kin, const float* __restrict__ vin,
    const float* __restrict__ kv_mask)
{
    __shared__ float ks[32][64];
    __shared__ float vs[32][64];

    const int nh = blockIdx.x;
    const int n = nh >> 3, h = nh & 7;
    const int s0 = blockIdx.y * 256;
    const int t = threadIdx.x;
    const int tx = t & 7, ty = t >> 3;

    u64 acc2[8][4] = {};
    float ksl = 0.f;

    #pragma unroll 1
    for (int tile = 0; tile < 8; tile++) {
        #pragma unroll
        for (int e = 0; e < 8; e++) {
            int idx = t + e * 64;
            int r = idx >> 4, c4 = (idx & 15) * 4;
            int s = s0 + tile * 32 + r;
            float m = kv_mask[n * SSZ + s];
            size_t g = (((size_t)(n * SSZ + s)) * HH + h) * DD + c4;
            float4 kq = *(const float4*)&kin[g];
            float4 vq = *(const float4*)&vin[g];
            *(float4*)&ks[r][c4] = make_float4(fmap(kq.x) * m, fmap(kq.y) * m,
                                               fmap(kq.z) * m, fmap(kq.w) * m);
            *(float4*)&vs[r][c4] = make_float4(vq.x * m, vq.y * m,
                                               vq.z * m, vq.w * m);
        }
        __syncthreads();

        #pragma unroll 4
        for (int s = 0; s < 32; s++) {
            float4 a0 = *(const float4*)&ks[s][ty * 4];
            float4 a1 = *(const float4*)&ks[s][32 + ty * 4];
            float4 b0 = *(const float4*)&vs[s][tx * 4];
            float4 b1 = *(const float4*)&vs[s][32 + tx * 4];
            ksl += ks[s][t];
            float a[8] = {a0.x, a0.y, a0.z, a0.w, a1.x, a1.y, a1.z, a1.w};
            u64 b2[4];
            b2[0] = ((const u64*)&b0)[0];
            b2[1] = ((const u64*)&b0)[1];
            b2[2] = ((const u64*)&b1)[0];
            b2[3] = ((const u64*)&b1)[1];
            #pragma unroll
            for (int i = 0; i < 8; i++) {
                u64 as = splat2(a[i]);
                #pragma unroll
                for (int j = 0; j < 4; j++)
                    acc2[i][j] = ffma2(as, b2[j], acc2[i][j]);
            }
        }
        __syncthreads();
    }

    float* part = &g_part[(nh * CH + blockIdx.y) * PART_STRIDE];
    #pragma unroll
    for (int i = 0; i < 8; i++) {
        int row = (i < 4) ? (ty * 4 + i) : (32 + ty * 4 + i - 4);
        float4 f0, f1;
        ((u64*)&f0)[0] = acc2[i][0];
        ((u64*)&f0)[1] = acc2[i][1];
        ((u64*)&f1)[0] = acc2[i][2];
        ((u64*)&f1)[1] = acc2[i][3];
        *(float4*)&part[row * 64 + tx * 4] = f0;
        *(float4*)&part[row * 64 + 32 + tx * 4] = f1;
    }
    part[4096 + t] = ksl;
}

// Reduce 32 partials -> final kv + ksum. 520*256 == 32*4160 exactly.
__global__ __launch_bounds__(256) void kv_reduce_kernel() {
    int idx = blockIdx.x * 256 + threadIdx.x;
    int nh = idx / PART_STRIDE;
    int el = idx - nh * PART_STRIDE;
    float s = 0.f;
    #pragma unroll 8
    for (int ch = 0; ch < CH; ch++)
        s += g_part[(nh * CH + ch) * PART_STRIDE + el];
    if (el < 4096) g_kv[nh * 4096 + el] = s;
    else           g_ksum[nh * 64 + el - 4096] = s;
}

// Kernel B: out = (qf . kv) / (qf . ksum + eps). 128 threads, 128 l-rows/CTA.
#define OUT_SMEM_BYTES (128 * QPAD * 4 + 64 * 64 * 4 + 64 * 4 + 128 * 4)

__global__ __launch_bounds__(128, 4) void out_kernel(
    const float* __restrict__ qin, const float* __restrict__ q_mask,
    float* __restrict__ out)
{
    extern __shared__ float dynbuf[];
    float (*qs)[QPAD] = (float(*)[QPAD])dynbuf;                  // 128*68
    float (*kvs)[64]  = (float(*)[64])(dynbuf + 128 * QPAD);    // 64*64
    float* ksum_s     = dynbuf + 128 * QPAD + 64 * 64;          // 64
    float* div_s      = ksum_s + 64;                            // 128

    const int nh = blockIdx.x;
    const int n = nh >> 3, h = nh & 7;
    const int l0 = blockIdx.y * 128;
    const int t = threadIdx.x;
    const int tx = t & 7;
    const int tyg = t >> 3;   // 0..15

    const float4* kvg = (const float4*)&g_kv[nh * 4096];
    #pragma unroll
    for (int e = 0; e < 8; e++)
        ((float4*)kvs)[t + e * 128] = kvg[t + e * 128];
    if (t < 64) ksum_s[t] = g_ksum[nh * 64 + t];

    #pragma unroll
    for (int e = 0; e < 16; e++) {
        int idx = t + e * 128;
        int l = idx >> 4, c4 = (idx & 15) * 4;
        float m = q_mask[n * LL + l0 + l];
        size_t g = (((size_t)(n * LL + l0 + l)) * HH + h) * DD + c4;
        float4 x = *(const float4*)&qin[g];
        *(float4*)&qs[l][c4] = make_float4(fmap(x.x) * m, fmap(x.y) * m,
                                           fmap(x.z) * m, fmap(x.w) * m);
    }
    __syncthreads();

    {
        float p = 0.f;
        #pragma unroll 16
        for (int d = 0; d < 64; d++)
            p += qs[t][d] * ksum_s[d];
        div_s[t] = 1.f / (p + EPS);
    }
    __syncthreads();

    u64 acc2[8][4] = {};
    #pragma unroll 2
    for (int d4 = 0; d4 < 64; d4 += 4) {
        // a-fragments: 8 q-rows x 4 d's, one LDS.128 per row
        float4 a[8];
        #pragma unroll
        for (int i = 0; i < 8; i++) {
            int row = (i < 4) ? (tyg * 4 + i) : (64 + tyg * 4 + i - 4);
            a[i] = *(const float4*)&qs[row][d4];
        }
        #pragma unroll
        for (int dd = 0; dd < 4; dd++) {
            float4 b0 = *(const float4*)&kvs[d4 + dd][tx * 4];
            float4 b1 = *(const float4*)&kvs[d4 + dd][32 + tx * 4];
            u64 b2[4];
            b2[0] = ((const u64*)&b0)[0];
            b2[1] = ((const u64*)&b0)[1];
            b2[2] = ((const u64*)&b1)[0];
            b2[3] = ((const u64*)&b1)[1];
            #pragma unroll
            for (int i = 0; i < 8; i++) {
                u64 as = splat2(((const float*)&a[i])[dd]);
                #pragma unroll
                for (int j = 0; j < 4; j++)
                    acc2[i][j] = ffma2(as, b2[j], acc2[i][j]);
            }
        }
    }

    #pragma unroll
    for (int i = 0; i < 8; i++) {
        int rl = (i < 4) ? (tyg * 4 + i) : (64 + tyg * 4 + i - 4);
        int l = l0 + rl;
        float dv = div_s[rl];
        float4 f0, f1;
        ((u64*)&f0)[0] = acc2[i][0];
        ((u64*)&f0)[1] = acc2[i][1];
        ((u64*)&f1)[0] = acc2[i][2];
        ((u64*)&f1)[1] = acc2[i][3];
        f0.x *= dv; f0.y *= dv; f0.z *= dv; f0.w *= dv;
        f1.x *= dv; f1.y *= dv; f1.z *= dv; f1.w *= dv;
        size_t g = (((size_t)(n * LL + l)) * HH + h) * DD;
        *(float4*)&out[g + tx * 4] = f0;
        *(float4*)&out[g + 32 + tx * 4] = f1;
    }
}

extern "C" void kernel_launch(void* const* d_in, const int* in_sizes, int n_in,
                              void* d_out, int out_size)
{
    const float* q   = (const float*)d_in[0];
    const float* k   = (const float*)d_in[1];
    const float* v   = (const float*)d_in[2];
    const float* qm  = (const float*)d_in[3];
    const float* kvm = (const float*)d_in[4];
    float* out = (float*)d_out;

    static bool attr_done = false;
    if (!attr_done) {
        cudaFuncSetAttribute(out_kernel,
                             cudaFuncAttributeMaxDynamicSharedMemorySize,
                             OUT_SMEM_BYTES);
        attr_done = true;
    }

    kv_partial_kernel<<<dim3(NH, CH), 64>>>(k, v, kvm);
    kv_reduce_kernel<<<(NH * PART_STRIDE) / 256, 256>>>();
    out_kernel<<<dim3(NH, 64), 128, OUT_SMEM_BYTES>>>(q, qm, out);
}